// round 15
// baseline (speedup 1.0000x reference)
#include <cuda_runtime.h>
#include <cuda_fp16.h>
#include <cstdint>
#include <math.h>

#define BATCH 2
#define SEQ   2048
#define EMB   1024
#define NHEAD 16
#define HDIM  64
#define M_ROWS (BATCH*SEQ)      // 4096
#define QKV_N  (3*EMB)          // 3072

// ---------------- scratch (device globals, no allocation) ----------------
__device__ float  g_T[HDIM*HDIM];
__device__ float  g_Wf[EMB*QKV_N];               // folded fp32 [E][3E]
__device__ float  g_bf[QKV_N];
__device__ __half g_xh[(size_t)M_ROWS*EMB];      // fp16(x)
__device__ __half g_WfT[(size_t)QKV_N*EMB];      // folded weights^T fp16 [3E][E]
__device__ __half g_WoT[(size_t)EMB*EMB];        // Wout^T fp16 [E][E]
__device__ __half g_qkh[(size_t)M_ROWS*2048];    // q|k fp16 [token][2048]
__device__ float  g_v[(size_t)M_ROWS*EMB];       // v fp32 [token][1024]
__device__ __half g_vT[(size_t)32*64*SEQ];       // V^T fp16 [bh][d][s]
__device__ __half g_attnh[(size_t)M_ROWS*EMB];   // attention out fp16

__device__ __forceinline__ unsigned packh2(float lo, float hi) {
    __half2 h = __floats2half2_rn(lo, hi);
    return *(unsigned*)&h;
}

__device__ __forceinline__ uint32_t smem_u32(const void* p) {
    uint32_t a;
    asm("{ .reg .u64 t; cvta.to.shared.u64 t, %1; cvt.u32.u64 %0, t; }"
        : "=r"(a) : "l"(p));
    return a;
}

__device__ __forceinline__ void cp16(uint32_t dst, const void* src) {
    asm volatile("cp.async.cg.shared.global [%0], [%1], 16;" :: "r"(dst), "l"(src));
}
#define CP_COMMIT() asm volatile("cp.async.commit_group;" ::: "memory")
#define CP_WAIT(n)  asm volatile("cp.async.wait_group %0;" :: "n"(n) : "memory")

__device__ __forceinline__ void mma_f16(float c[4],
                                        unsigned a0, unsigned a1, unsigned a2, unsigned a3,
                                        unsigned b0, unsigned b1) {
    asm volatile(
        "mma.sync.aligned.m16n8k16.row.col.f32.f16.f16.f32 "
        "{%0,%1,%2,%3}, {%4,%5,%6,%7}, {%8,%9}, {%0,%1,%2,%3};"
        : "+f"(c[0]), "+f"(c[1]), "+f"(c[2]), "+f"(c[3])
        : "r"(a0), "r"(a1), "r"(a2), "r"(a3), "r"(b0), "r"(b1));
}

// ---------------- build T = I + (alpha/64) * H diag H --------------------
__global__ void build_T_kernel(const float* __restrict__ diag,
                               const float* __restrict__ alpha_p) {
    int i = blockIdx.x, j = threadIdx.x;
    float a = alpha_p[0] * (1.0f / 64.0f);
    int ij = i ^ j;
    float acc = 0.f;
    #pragma unroll
    for (int k = 0; k < 64; k++)
        acc += diag[k] * ((__popc(ij & k) & 1) ? -1.f : 1.f);
    g_T[i*64 + j] = a * acc + ((i == j) ? 1.f : 0.f);
}

// ---------------- fold T into QKV weights (fp32 out) ----------------------
__global__ void fold_w_kernel(const float* __restrict__ W) {
    int c = blockIdx.x * blockDim.x + threadIdx.x;
    int e = blockIdx.y;
    if (c >= QKV_N) return;
    size_t row = (size_t)e * QKV_N;
    if (c < 2*EMB) {
        int j = c & 63;
        int base = c - j;
        float acc = 0.f;
        #pragma unroll 8
        for (int d = 0; d < 64; d++)
            acc += W[row + base + d] * g_T[d*64 + j];
        g_Wf[row + c] = acc;
    } else {
        g_Wf[row + c] = W[row + c];
    }
}

__global__ void fold_b_kernel(const float* __restrict__ bqkv,
                              const float* __restrict__ bias_h) {
    int c = blockIdx.x * blockDim.x + threadIdx.x;
    if (c >= QKV_N) return;
    if (c < 2*EMB) {
        int j = c & 63;
        int base = c - j;
        float acc = bias_h[j];
        #pragma unroll 8
        for (int d = 0; d < 64; d++)
            acc += bqkv[base + d] * g_T[d*64 + j];
        g_bf[c] = acc;
    } else {
        g_bf[c] = bqkv[c];
    }
}

// ---------------- elementwise fp32 -> fp16 ---------------------------------
__global__ void h16_kernel(const float* __restrict__ in, __half* __restrict__ out, int n4) {
    int i = blockIdx.x * blockDim.x + threadIdx.x;
    if (i >= n4) return;
    float4 v = ((const float4*)in)[i];
    __half2 h0 = __floats2half2_rn(v.x, v.y);
    __half2 h1 = __floats2half2_rn(v.z, v.w);
    uint2 u; u.x = *(unsigned*)&h0; u.y = *(unsigned*)&h1;
    ((uint2*)out)[i] = u;
}

// ---------------- tiled transpose fp32 [R][C] -> fp16 [C][R] ---------------
__global__ void transpose_h_kernel(const float* __restrict__ in,
                                   __half* __restrict__ out, int R, int C) {
    __shared__ float t[32][33];
    int c0 = blockIdx.x * 32, r0 = blockIdx.y * 32;
    int x = threadIdx.x, y = threadIdx.y;   // 32 x 8
    #pragma unroll
    for (int i = 0; i < 32; i += 8)
        t[y+i][x] = in[(size_t)(r0 + y + i) * C + c0 + x];
    __syncthreads();
    #pragma unroll
    for (int i = 0; i < 32; i += 8)
        out[(size_t)(c0 + y + i) * R + r0 + x] = __float2half_rn(t[x][y+i]);
}

// ---------------- V transpose: g_v fp32 [tok][1024] -> g_vT fp16 [bh][d][s]
__global__ void vT_kernel() {
    __shared__ float t[32][33];
    int bh = blockIdx.z;
    int b = bh >> 4, h = bh & 15;
    int dt = blockIdx.y;
    int st = blockIdx.x;
    int x = threadIdx.x, y = threadIdx.y;
    #pragma unroll
    for (int i = 0; i < 32; i += 8)
        t[y+i][x] = g_v[(size_t)(b*SEQ + st*32 + y + i)*EMB + h*64 + dt*32 + x];
    __syncthreads();
    #pragma unroll
    for (int i = 0; i < 32; i += 8)
        g_vT[(size_t)(bh*64 + dt*32 + y + i)*SEQ + st*32 + x] = __float2half_rn(t[x][y+i]);
}

// ---------------- fp16 GEMM: C = A @ B'^T + bias (R14-proven form) --------
#define APH 20
#define ASTGH (128*APH)
#define BSTGH (256*APH)
#define GSTGH (ASTGH + BSTGH)
#define GEMM_SMEM (3*GSTGH*4)
__global__ __launch_bounds__(256, 1)
void gemm_f16_kernel(const __half* __restrict__ A,
                     const __half* __restrict__ B,
                     const float* __restrict__ bias,
                     float* __restrict__ C,
                     __half* __restrict__ Ch,
                     int M, int N, int K, int mode) {
    extern __shared__ unsigned sh[];
    uint32_t shA = smem_u32(sh);

    int tid = threadIdx.x;
    int warp = tid >> 5, lane = tid & 31;
    int tig = lane & 3, gid = lane >> 2;
    int warpM = warp & 1, warpN = warp >> 1;
    int m0 = blockIdx.y * 128;
    int n0 = blockIdx.x * 256;

    float c[4][8][4];
    #pragma unroll
    for (int mf = 0; mf < 4; mf++)
        #pragma unroll
        for (int nf = 0; nf < 8; nf++)
            #pragma unroll
            for (int j = 0; j < 4; j++) c[mf][nf][j] = 0.f;

    int nk = K / 32;

    auto issue = [&](int s, int k0) {
        uint32_t base = shA + (uint32_t)s * GSTGH * 4;
        #pragma unroll
        for (int i = 0; i < 2; i++) {
            int li = tid + i*256;
            int row = li >> 2, c8 = (li & 3) * 8;
            cp16(base + (row*APH + c8/2)*4, A + (size_t)(m0 + row)*K + k0 + c8);
        }
        #pragma unroll
        for (int i = 0; i < 4; i++) {
            int li = tid + i*256;
            int row = li >> 2, c8 = (li & 3) * 8;
            cp16(base + (ASTGH + row*APH + c8/2)*4, B + (size_t)(n0 + row)*K + k0 + c8);
        }
        CP_COMMIT();
    };

    issue(0, 0);
    issue(1, 32);

    for (int kt = 0; kt < nk; kt++) {
        if (kt + 2 < nk) {
            issue((kt + 2) % 3, (kt + 2) * 32);
            CP_WAIT(2);
        } else if (kt + 1 < nk) {
            CP_WAIT(1);
        } else {
            CP_WAIT(0);
        }
        __syncthreads();

        unsigned* Ab = sh + (kt % 3) * GSTGH;
        unsigned* Bb = Ab + ASTGH;

        #pragma unroll
        for (int kw = 0; kw < 16; kw += 8) {
            unsigned af[4][4];
            #pragma unroll
            for (int mf = 0; mf < 4; mf++) {
                int m = warpM*64 + mf*16 + gid;
                af[mf][0] = Ab[m*APH + kw + tig];
                af[mf][1] = Ab[(m+8)*APH + kw + tig];
                af[mf][2] = Ab[m*APH + kw + 4 + tig];
                af[mf][3] = Ab[(m+8)*APH + kw + 4 + tig];
            }
            unsigned bf[8][2];
            #pragma unroll
            for (int nf = 0; nf < 8; nf++) {
                int n = warpN*64 + nf*8 + gid;
                bf[nf][0] = Bb[n*APH + kw + tig];
                bf[nf][1] = Bb[n*APH + kw + 4 + tig];
            }
            #pragma unroll
            for (int mf = 0; mf < 4; mf++)
                #pragma unroll
                for (int nf = 0; nf < 8; nf++)
                    mma_f16(c[mf][nf], af[mf][0], af[mf][1], af[mf][2], af[mf][3],
                            bf[nf][0], bf[nf][1]);
        }
        __syncthreads();
    }

    #pragma unroll
    for (int mf = 0; mf < 4; mf++) {
        int row = m0 + warpM*64 + mf*16 + gid;
        #pragma unroll
        for (int nf = 0; nf < 8; nf++) {
            int col = n0 + warpN*64 + nf*8 + 2*tig;
            float b0 = bias[col], b1 = bias[col+1];
            float v00 = c[mf][nf][0] + b0, v01 = c[mf][nf][1] + b1;
            float v10 = c[mf][nf][2] + b0, v11 = c[mf][nf][3] + b1;
            if (mode == 1) {
                if (col < 2*EMB) {
                    __half2 h0 = __floats2half2_rn(v00, v01);
                    __half2 h1 = __floats2half2_rn(v10, v11);
                    *(__half2*)&Ch[(size_t)row * 2048 + col]     = h0;
                    *(__half2*)&Ch[(size_t)(row+8) * 2048 + col] = h1;
                } else {
                    int cv = col - 2*EMB;
                    *(float2*)&C[(size_t)row * EMB + cv]     = make_float2(v00, v01);
                    *(float2*)&C[(size_t)(row+8) * EMB + cv] = make_float2(v10, v11);
                }
            } else {
                *(float2*)&C[(size_t)row * N + col]     = make_float2(v00, v01);
                *(float2*)&C[(size_t)(row+8) * N + col] = make_float2(v10, v11);
            }
        }
    }
}

// ---------------- flash attention, fp16, Bq=256, 8 warps x 32 rows --------
// 16 warps/SM at 2 CTAs -> 4/SMSP latency hiding, K/V frag reuse kept.
#define PW 36
#define KSTG (64*PW)
#define VSTG (64*PW)
#define ATTN_SMEM ((256*PW + 2*KSTG + 2*VSTG)*4 + 2*64*4)
__global__ __launch_bounds__(256, 2)
void attn_f16_kernel(const int* __restrict__ mask) {
    extern __shared__ unsigned smU[];
    unsigned* Qs = smU;                     // [256][36w]
    unsigned* Ks = Qs + 256*PW;             // [2][64][36w]
    unsigned* Vs = Ks + 2*KSTG;             // [2][64][36w] (V^T tiles)
    int*      Ms = (int*)(Vs + 2*VSTG);     // [2][64]

    uint32_t kA = smem_u32(Ks);
    uint32_t vA = smem_u32(Vs);
    uint32_t mA = smem_u32(Ms);

    int bh = blockIdx.x;
    int b = bh >> 4, h = bh & 15;
    int q0 = blockIdx.y * 256;

    int tid = threadIdx.x;
    int warp = tid >> 5, lane = tid & 31;
    int tig = lane & 3, gid = lane >> 2;
    int rbase = warp * 32;

    const __half* qbaseH = g_qkh + (size_t)(b*SEQ)*2048 + h*HDIM;
    const __half* kbaseH = g_qkh + (size_t)(b*SEQ)*2048 + 1024 + h*HDIM;
    const __half* vTbase = g_vT + (size_t)(bh*64)*SEQ;
    const int*    mrow   = mask + b*SEQ;

    auto issue = [&](int s, int k0) {
        #pragma unroll
        for (int i = 0; i < 2; i++) {
            int li = tid + i*256;
            int r = li >> 3, c8 = (li & 7) * 8;   // 64 rows x 8 cp16
            cp16(kA + (s*KSTG + r*PW + c8/2)*4, kbaseH + (size_t)(k0 + r)*2048 + c8);
            cp16(vA + (s*VSTG + r*PW + c8/2)*4, vTbase + (size_t)r*SEQ + k0 + c8);
        }
        if (tid < 16) cp16(mA + s*256 + tid*16, mrow + k0 + tid*4);
        CP_COMMIT();
    };

    // load Q tile (fp16, 256 rows x 64 halves)
    #pragma unroll
    for (int i = 0; i < 8; i++) {
        int li = tid + i*256;
        int r = li >> 3, c8 = (li & 7) * 8;
        uint4 v = *(const uint4*)&qbaseH[(size_t)(q0 + r)*2048 + c8];
        *(uint4*)&Qs[r*PW + c8/2] = v;
    }

    issue(0, 0);
    issue(1, 64);

    float o[2][8][4];
    float m0r[2], m1r[2], l0[2], l1[2];
    #pragma unroll
    for (int sl = 0; sl < 2; sl++) {
        m0r[sl] = -1e30f; m1r[sl] = -1e30f; l0[sl] = 0.f; l1[sl] = 0.f;
        #pragma unroll
        for (int nf = 0; nf < 8; nf++)
            #pragma unroll
            for (int j = 0; j < 4; j++) o[sl][nf][j] = 0.f;
    }

    const int NT = SEQ / 64;
    for (int kt = 0; kt < NT; kt++) {
        int st = kt & 1;
        if (kt + 1 < NT) { CP_WAIT(1); } else { CP_WAIT(0); }
        __syncthreads();

        unsigned* Kb = Ks + st*KSTG;
        unsigned* Vb = Vs + st*VSTG;
        int*      Mb = Ms + st*64;

        // S = Q K^T  (fp16 k16), K frags shared across slabs
        float s[2][8][4];
        #pragma unroll
        for (int sl = 0; sl < 2; sl++)
            #pragma unroll
            for (int nf = 0; nf < 8; nf++)
                #pragma unroll
                for (int j = 0; j < 4; j++) s[sl][nf][j] = 0.f;
        #pragma unroll
        for (int kk = 0; kk < 64; kk += 16) {
            int kw = kk >> 1;
            unsigned a[2][4];
            #pragma unroll
            for (int sl = 0; sl < 2; sl++) {
                int rA = rbase + 16*sl + gid;
                a[sl][0] = Qs[rA*PW + kw + tig];
                a[sl][1] = Qs[(rA+8)*PW + kw + tig];
                a[sl][2] = Qs[rA*PW + kw + 4 + tig];
                a[sl][3] = Qs[(rA+8)*PW + kw + 4 + tig];
            }
            #pragma unroll
            for (int nf = 0; nf < 8; nf++) {
                unsigned b0 = Kb[(nf*8 + gid)*PW + kw + tig];
                unsigned b1 = Kb[(nf*8 + gid)*PW + kw + 4 + tig];
                mma_f16(s[0][nf], a[0][0], a[0][1], a[0][2], a[0][3], b0, b1);
                mma_f16(s[1][nf], a[1][0], a[1][1], a[1][2], a[1][3], b0, b1);
            }
        }

        // mask + scale + online softmax + fp16 pack, per slab
        unsigned ph[2][8][2];
        #pragma unroll
        for (int sl = 0; sl < 2; sl++) {
            #pragma unroll
            for (int nf = 0; nf < 8; nf++) {
                int col = nf*8 + 2*tig;
                int mv0 = Mb[col], mv1 = Mb[col+1];
                s[sl][nf][0] = mv0 ? s[sl][nf][0]*0.125f : -1e30f;
                s[sl][nf][1] = mv1 ? s[sl][nf][1]*0.125f : -1e30f;
                s[sl][nf][2] = mv0 ? s[sl][nf][2]*0.125f : -1e30f;
                s[sl][nf][3] = mv1 ? s[sl][nf][3]*0.125f : -1e30f;
            }
            float rm0 = -1e30f, rm1 = -1e30f;
            #pragma unroll
            for (int nf = 0; nf < 8; nf++) {
                rm0 = fmaxf(rm0, fmaxf(s[sl][nf][0], s[sl][nf][1]));
                rm1 = fmaxf(rm1, fmaxf(s[sl][nf][2], s[sl][nf][3]));
            }
            rm0 = fmaxf(rm0, __shfl_xor_sync(0xffffffffu, rm0, 1));
            rm0 = fmaxf(rm0, __shfl_xor_sync(0xffffffffu, rm0, 2));
            rm1 = fmaxf(rm1, __shfl_xor_sync(0xffffffffu, rm1, 1));
            rm1 = fmaxf(rm1, __shfl_xor_sync(0xffffffffu, rm1, 2));

            float mn0 = fmaxf(m0r[sl], rm0), mn1 = fmaxf(m1r[sl], rm1);
            float sc0 = __expf(m0r[sl] - mn0), sc1 = __expf(m1r[sl] - mn1);
            m0r[sl] = mn0; m1r[sl] = mn1;

            float rs0 = 0.f, rs1 = 0.f;
            #pragma unroll
            for (int nf = 0; nf < 8; nf++) {
                s[sl][nf][0] = __expf(s[sl][nf][0] - mn0);
                s[sl][nf][1] = __expf(s[sl][nf][1] - mn0);
                s[sl][nf][2] = __expf(s[sl][nf][2] - mn1);
                s[sl][nf][3] = __expf(s[sl][nf][3] - mn1);
                rs0 += s[sl][nf][0] + s[sl][nf][1];
                rs1 += s[sl][nf][2] + s[sl][nf][3];
            }
            rs0 += __shfl_xor_sync(0xffffffffu, rs0, 1);
            rs0 += __shfl_xor_sync(0xffffffffu, rs0, 2);
            rs1 += __shfl_xor_sync(0xffffffffu, rs1, 1);
            rs1 += __shfl_xor_sync(0xffffffffu, rs1, 2);
            l0[sl] = l0[sl]*sc0 + rs0;
            l1[sl] = l1[sl]*sc1 + rs1;

            #pragma unroll
            for (int nf = 0; nf < 8; nf++) {
                o[sl][nf][0] *= sc0; o[sl][nf][1] *= sc0;
                o[sl][nf][2] *= sc1; o[sl][nf][3] *= sc1;
                ph[sl][nf][0] = packh2(s[sl][nf][0], s[sl][nf][1]);
                ph[sl][nf][1] = packh2(s[sl][nf][2], s[sl][nf][3]);
            }
        }

        // O += P @ V : register A-frags, V frags shared across slabs
        #pragma unroll
        for (int kk = 0; kk < 64; kk += 16) {
            int g0 = kk >> 3, g1 = g0 + 1;
            int kw = kk >> 1;
            #pragma unroll
            for (int nf = 0; nf < 8; nf++) {
                unsigned b0 = Vb[(nf*8 + gid)*PW + kw + tig];
                unsigned b1 = Vb[(nf*8 + gid)*PW + kw + 4 + tig];
                mma_f16(o[0][nf], ph[0][g0][0], ph[0][g0][1], ph[0][g1][0], ph[0][g1][1], b0, b1);
                mma_f16(o[1][nf], ph[1][g0][0], ph[1][g0][1], ph[1][g1][0], ph[1][g1][1], b0, b1);
            }
        }
        __syncthreads();
        if (kt + 2 < NT) issue(st, (kt + 2) * 64);
    }

    // epilogue: normalize, write fp16
    #pragma unroll
    for (int sl = 0; sl < 2; sl++) {
        float inv0 = 1.f / l0[sl], inv1 = 1.f / l1[sl];
        int rA = rbase + sl*16 + gid, rB = rA + 8;
        #pragma unroll
        for (int nf = 0; nf < 8; nf++) {
            int col = nf*8 + 2*tig;
            size_t orow0 = (size_t)(b*SEQ + q0 + rA) * EMB + h*HDIM + col;
            size_t orow1 = (size_t)(b*SEQ + q0 + rB) * EMB + h*HDIM + col;
            __half2 h0 = __floats2half2_rn(o[sl][nf][0]*inv0, o[sl][nf][1]*inv0);
            __half2 h1 = __floats2half2_rn(o[sl][nf][2]*inv1, o[sl][nf][3]*inv1);
            *(__half2*)&g_attnh[orow0] = h0;
            *(__half2*)&g_attnh[orow1] = h1;
        }
    }
}

// ---------------- launch ---------------------------------------------------
extern "C" void kernel_launch(void* const* d_in, const int* in_sizes, int n_in,
                              void* d_out, int out_size) {
    const float* x      = (const float*)d_in[0];
    const int*   mask   = (const int*)  d_in[1];
    const float* Wqkv   = (const float*)d_in[2];
    const float* bqkv   = (const float*)d_in[3];
    const float* Wout   = (const float*)d_in[4];
    const float* bout   = (const float*)d_in[5];
    const float* diag   = (const float*)d_in[6];
    const float* alpha  = (const float*)d_in[7];
    const float* bias_h = (const float*)d_in[8];
    float* out = (float*)d_out;

    float*  vbuf;  cudaGetSymbolAddress((void**)&vbuf,  g_v);
    float*  Wf;    cudaGetSymbolAddress((void**)&Wf,    g_Wf);
    float*  bf;    cudaGetSymbolAddress((void**)&bf,    g_bf);
    __half* xh;    cudaGetSymbolAddress((void**)&xh,    g_xh);
    __half* WfT;   cudaGetSymbolAddress((void**)&WfT,   g_WfT);
    __half* WoT;   cudaGetSymbolAddress((void**)&WoT,   g_WoT);
    __half* qkh;   cudaGetSymbolAddress((void**)&qkh,   g_qkh);
    __half* attnh; cudaGetSymbolAddress((void**)&attnh, g_attnh);

    build_T_kernel<<<64, 64>>>(diag, alpha);
    {
        dim3 grid((QKV_N + 255)/256, EMB);
        fold_w_kernel<<<grid, 256>>>(Wqkv);
        fold_b_kernel<<<(QKV_N + 255)/256, 256>>>(bqkv, bias_h);
        int n4x = M_ROWS*EMB/4;
        h16_kernel<<<(n4x + 255)/256, 256>>>(x, xh, n4x);
        dim3 blk(32, 8);
        dim3 g1(QKV_N/32, EMB/32);
        transpose_h_kernel<<<g1, blk>>>(Wf, WfT, EMB, QKV_N);
        dim3 g2(EMB/32, EMB/32);
        transpose_h_kernel<<<g2, blk>>>(Wout, WoT, EMB, EMB);
    }

    cudaFuncSetAttribute(gemm_f16_kernel,
                         cudaFuncAttributeMaxDynamicSharedMemorySize, GEMM_SMEM);
    {   // QKV GEMM fp16: q/k -> g_qkh, v -> g_v
        dim3 grid(QKV_N/256, M_ROWS/128);
        gemm_f16_kernel<<<grid, 256, GEMM_SMEM>>>(xh, WfT, bf, vbuf, qkh,
                                                  M_ROWS, QKV_N, EMB, 1);
    }
    {   // V transpose -> g_vT
        dim3 blk(32, 8);
        dim3 grid(SEQ/32, 2, 32);
        vT_kernel<<<grid, blk>>>();
    }
    {   // attention (fp16, Bq=256)
        cudaFuncSetAttribute(attn_f16_kernel,
                             cudaFuncAttributeMaxDynamicSharedMemorySize, ATTN_SMEM);
        dim3 grid(BATCH*NHEAD, SEQ/256);
        attn_f16_kernel<<<grid, 256, ATTN_SMEM>>>(mask);
    }
    {   // output projection fp16 -> fp32 out
        dim3 grid(EMB/256, M_ROWS/128);
        gemm_f16_kernel<<<grid, 256, GEMM_SMEM>>>(attnh, WoT, bout, out, nullptr,
                                                  M_ROWS, EMB, EMB, 0);
    }
}

// round 16
// speedup vs baseline: 1.1815x; 1.1815x over previous
#include <cuda_runtime.h>
#include <cuda_fp16.h>
#include <cstdint>
#include <math.h>

#define BATCH 2
#define SEQ   2048
#define EMB   1024
#define NHEAD 16
#define HDIM  64
#define M_ROWS (BATCH*SEQ)      // 4096
#define QKV_N  (3*EMB)          // 3072

// ---------------- scratch (device globals, no allocation) ----------------
__device__ float  g_T[HDIM*HDIM];
__device__ float  g_Wf[EMB*QKV_N];               // folded fp32 [E][3E]
__device__ float  g_bf[QKV_N];
__device__ __half g_xh[(size_t)M_ROWS*EMB];      // fp16(x)
__device__ __half g_WfT[(size_t)QKV_N*EMB];      // folded weights^T fp16 [3E][E]
__device__ __half g_WoT[(size_t)EMB*EMB];        // Wout^T fp16 [E][E]
__device__ __half g_qkh[(size_t)M_ROWS*2048];    // q|k fp16 [token][2048]
__device__ float  g_v[(size_t)M_ROWS*EMB];       // v fp32 [token][1024]
__device__ __half g_vT[(size_t)32*64*SEQ];       // V^T fp16 [bh][d][s]
__device__ __half g_attnh[(size_t)M_ROWS*EMB];   // attention out fp16

__device__ __forceinline__ unsigned packh2(float lo, float hi) {
    __half2 h = __floats2half2_rn(lo, hi);
    return *(unsigned*)&h;
}

__device__ __forceinline__ uint32_t smem_u32(const void* p) {
    uint32_t a;
    asm("{ .reg .u64 t; cvta.to.shared.u64 t, %1; cvt.u32.u64 %0, t; }"
        : "=r"(a) : "l"(p));
    return a;
}

__device__ __forceinline__ void cp16(uint32_t dst, const void* src) {
    asm volatile("cp.async.cg.shared.global [%0], [%1], 16;" :: "r"(dst), "l"(src));
}
#define CP_COMMIT() asm volatile("cp.async.commit_group;" ::: "memory")
#define CP_WAIT(n)  asm volatile("cp.async.wait_group %0;" :: "n"(n) : "memory")

__device__ __forceinline__ void mma_f16(float c[4],
                                        unsigned a0, unsigned a1, unsigned a2, unsigned a3,
                                        unsigned b0, unsigned b1) {
    asm volatile(
        "mma.sync.aligned.m16n8k16.row.col.f32.f16.f16.f32 "
        "{%0,%1,%2,%3}, {%4,%5,%6,%7}, {%8,%9}, {%0,%1,%2,%3};"
        : "+f"(c[0]), "+f"(c[1]), "+f"(c[2]), "+f"(c[3])
        : "r"(a0), "r"(a1), "r"(a2), "r"(a3), "r"(b0), "r"(b1));
}

// ---------------- build T = I + (alpha/64) * H diag H --------------------
__global__ void build_T_kernel(const float* __restrict__ diag,
                               const float* __restrict__ alpha_p) {
    int i = blockIdx.x, j = threadIdx.x;
    float a = alpha_p[0] * (1.0f / 64.0f);
    int ij = i ^ j;
    float acc = 0.f;
    #pragma unroll
    for (int k = 0; k < 64; k++)
        acc += diag[k] * ((__popc(ij & k) & 1) ? -1.f : 1.f);
    g_T[i*64 + j] = a * acc + ((i == j) ? 1.f : 0.f);
}

// ---------------- fold T into QKV weights (fp32 out) ----------------------
__global__ void fold_w_kernel(const float* __restrict__ W) {
    int c = blockIdx.x * blockDim.x + threadIdx.x;
    int e = blockIdx.y;
    if (c >= QKV_N) return;
    size_t row = (size_t)e * QKV_N;
    if (c < 2*EMB) {
        int j = c & 63;
        int base = c - j;
        float acc = 0.f;
        #pragma unroll 8
        for (int d = 0; d < 64; d++)
            acc += W[row + base + d] * g_T[d*64 + j];
        g_Wf[row + c] = acc;
    } else {
        g_Wf[row + c] = W[row + c];
    }
}

__global__ void fold_b_kernel(const float* __restrict__ bqkv,
                              const float* __restrict__ bias_h) {
    int c = blockIdx.x * blockDim.x + threadIdx.x;
    if (c >= QKV_N) return;
    if (c < 2*EMB) {
        int j = c & 63;
        int base = c - j;
        float acc = bias_h[j];
        #pragma unroll 8
        for (int d = 0; d < 64; d++)
            acc += bqkv[base + d] * g_T[d*64 + j];
        g_bf[c] = acc;
    } else {
        g_bf[c] = bqkv[c];
    }
}

// ---------------- elementwise fp32 -> fp16 ---------------------------------
__global__ void h16_kernel(const float* __restrict__ in, __half* __restrict__ out, int n4) {
    int i = blockIdx.x * blockDim.x + threadIdx.x;
    if (i >= n4) return;
    float4 v = ((const float4*)in)[i];
    __half2 h0 = __floats2half2_rn(v.x, v.y);
    __half2 h1 = __floats2half2_rn(v.z, v.w);
    uint2 u; u.x = *(unsigned*)&h0; u.y = *(unsigned*)&h1;
    ((uint2*)out)[i] = u;
}

// ---------------- tiled transpose fp32 [R][C] -> fp16 [C][R] ---------------
__global__ void transpose_h_kernel(const float* __restrict__ in,
                                   __half* __restrict__ out, int R, int C) {
    __shared__ float t[32][33];
    int c0 = blockIdx.x * 32, r0 = blockIdx.y * 32;
    int x = threadIdx.x, y = threadIdx.y;   // 32 x 8
    #pragma unroll
    for (int i = 0; i < 32; i += 8)
        t[y+i][x] = in[(size_t)(r0 + y + i) * C + c0 + x];
    __syncthreads();
    #pragma unroll
    for (int i = 0; i < 32; i += 8)
        out[(size_t)(c0 + y + i) * R + r0 + x] = __float2half_rn(t[x][y+i]);
}

// ---------------- V transpose: g_v fp32 [tok][1024] -> g_vT fp16 [bh][d][s]
__global__ void vT_kernel() {
    __shared__ float t[32][33];
    int bh = blockIdx.z;
    int b = bh >> 4, h = bh & 15;
    int dt = blockIdx.y;
    int st = blockIdx.x;
    int x = threadIdx.x, y = threadIdx.y;
    #pragma unroll
    for (int i = 0; i < 32; i += 8)
        t[y+i][x] = g_v[(size_t)(b*SEQ + st*32 + y + i)*EMB + h*64 + dt*32 + x];
    __syncthreads();
    #pragma unroll
    for (int i = 0; i < 32; i += 8)
        g_vT[(size_t)(bh*64 + dt*32 + y + i)*SEQ + st*32 + x] = __float2half_rn(t[x][y+i]);
}

// ---------------- fp16 GEMM: C = A @ B'^T + bias (R14-proven form) --------
#define APH 20
#define ASTGH (128*APH)
#define BSTGH (256*APH)
#define GSTGH (ASTGH + BSTGH)
#define GEMM_SMEM (3*GSTGH*4)
__global__ __launch_bounds__(256, 1)
void gemm_f16_kernel(const __half* __restrict__ A,
                     const __half* __restrict__ B,
                     const float* __restrict__ bias,
                     float* __restrict__ C,
                     __half* __restrict__ Ch,
                     int M, int N, int K, int mode) {
    extern __shared__ unsigned sh[];
    uint32_t shA = smem_u32(sh);

    int tid = threadIdx.x;
    int warp = tid >> 5, lane = tid & 31;
    int tig = lane & 3, gid = lane >> 2;
    int warpM = warp & 1, warpN = warp >> 1;
    int m0 = blockIdx.y * 128;
    int n0 = blockIdx.x * 256;

    float c[4][8][4];
    #pragma unroll
    for (int mf = 0; mf < 4; mf++)
        #pragma unroll
        for (int nf = 0; nf < 8; nf++)
            #pragma unroll
            for (int j = 0; j < 4; j++) c[mf][nf][j] = 0.f;

    int nk = K / 32;

    auto issue = [&](int s, int k0) {
        uint32_t base = shA + (uint32_t)s * GSTGH * 4;
        #pragma unroll
        for (int i = 0; i < 2; i++) {
            int li = tid + i*256;
            int row = li >> 2, c8 = (li & 3) * 8;
            cp16(base + (row*APH + c8/2)*4, A + (size_t)(m0 + row)*K + k0 + c8);
        }
        #pragma unroll
        for (int i = 0; i < 4; i++) {
            int li = tid + i*256;
            int row = li >> 2, c8 = (li & 3) * 8;
            cp16(base + (ASTGH + row*APH + c8/2)*4, B + (size_t)(n0 + row)*K + k0 + c8);
        }
        CP_COMMIT();
    };

    issue(0, 0);
    issue(1, 32);

    for (int kt = 0; kt < nk; kt++) {
        if (kt + 2 < nk) {
            issue((kt + 2) % 3, (kt + 2) * 32);
            CP_WAIT(2);
        } else if (kt + 1 < nk) {
            CP_WAIT(1);
        } else {
            CP_WAIT(0);
        }
        __syncthreads();

        unsigned* Ab = sh + (kt % 3) * GSTGH;
        unsigned* Bb = Ab + ASTGH;

        #pragma unroll
        for (int kw = 0; kw < 16; kw += 8) {
            unsigned af[4][4];
            #pragma unroll
            for (int mf = 0; mf < 4; mf++) {
                int m = warpM*64 + mf*16 + gid;
                af[mf][0] = Ab[m*APH + kw + tig];
                af[mf][1] = Ab[(m+8)*APH + kw + tig];
                af[mf][2] = Ab[m*APH + kw + 4 + tig];
                af[mf][3] = Ab[(m+8)*APH + kw + 4 + tig];
            }
            unsigned bf[8][2];
            #pragma unroll
            for (int nf = 0; nf < 8; nf++) {
                int n = warpN*64 + nf*8 + gid;
                bf[nf][0] = Bb[n*APH + kw + tig];
                bf[nf][1] = Bb[n*APH + kw + 4 + tig];
            }
            #pragma unroll
            for (int mf = 0; mf < 4; mf++)
                #pragma unroll
                for (int nf = 0; nf < 8; nf++)
                    mma_f16(c[mf][nf], af[mf][0], af[mf][1], af[mf][2], af[mf][3],
                            bf[nf][0], bf[nf][1]);
        }
        __syncthreads();
    }

    #pragma unroll
    for (int mf = 0; mf < 4; mf++) {
        int row = m0 + warpM*64 + mf*16 + gid;
        #pragma unroll
        for (int nf = 0; nf < 8; nf++) {
            int col = n0 + warpN*64 + nf*8 + 2*tig;
            float b0 = bias[col], b1 = bias[col+1];
            float v00 = c[mf][nf][0] + b0, v01 = c[mf][nf][1] + b1;
            float v10 = c[mf][nf][2] + b0, v11 = c[mf][nf][3] + b1;
            if (mode == 1) {
                if (col < 2*EMB) {
                    __half2 h0 = __floats2half2_rn(v00, v01);
                    __half2 h1 = __floats2half2_rn(v10, v11);
                    *(__half2*)&Ch[(size_t)row * 2048 + col]     = h0;
                    *(__half2*)&Ch[(size_t)(row+8) * 2048 + col] = h1;
                } else {
                    int cv = col - 2*EMB;
                    *(float2*)&C[(size_t)row * EMB + cv]     = make_float2(v00, v01);
                    *(float2*)&C[(size_t)(row+8) * EMB + cv] = make_float2(v10, v11);
                }
            } else {
                *(float2*)&C[(size_t)row * N + col]     = make_float2(v00, v01);
                *(float2*)&C[(size_t)(row+8) * N + col] = make_float2(v10, v11);
            }
        }
    }
}

// ---------------- flash attention, fp16, Bq=128 (R13 form), 3-stage -------
#define PW 36
#define KSTG (64*PW)
#define VSTG (64*PW)
#define ATTN_SMEM ((128*PW + 3*KSTG + 3*VSTG)*4 + 3*64*4)
__global__ __launch_bounds__(128, 2)
void attn_f16_kernel(const int* __restrict__ mask) {
    extern __shared__ unsigned smU[];
    unsigned* Qs = smU;                     // [128][36w]
    unsigned* Ks = Qs + 128*PW;             // [3][64][36w]
    unsigned* Vs = Ks + 3*KSTG;             // [3][64][36w] (V^T tiles)
    int*      Ms = (int*)(Vs + 3*VSTG);     // [3][64]

    uint32_t kA = smem_u32(Ks);
    uint32_t vA = smem_u32(Vs);
    uint32_t mA = smem_u32(Ms);

    int bh = blockIdx.x;
    int b = bh >> 4, h = bh & 15;
    int q0 = blockIdx.y * 128;

    int tid = threadIdx.x;
    int warp = tid >> 5, lane = tid & 31;
    int tig = lane & 3, gid = lane >> 2;
    int rbase = warp * 32;

    const __half* qbaseH = g_qkh + (size_t)(b*SEQ)*2048 + h*HDIM;
    const __half* kbaseH = g_qkh + (size_t)(b*SEQ)*2048 + 1024 + h*HDIM;
    const __half* vTbase = g_vT + (size_t)(bh*64)*SEQ;
    const int*    mrow   = mask + b*SEQ;

    auto issue = [&](int s, int k0) {
        #pragma unroll
        for (int i = 0; i < 4; i++) {
            int li = tid + i*128;
            int r = li >> 3, c8 = (li & 7) * 8;
            cp16(kA + (s*KSTG + r*PW + c8/2)*4, kbaseH + (size_t)(k0 + r)*2048 + c8);
            cp16(vA + (s*VSTG + r*PW + c8/2)*4, vTbase + (size_t)r*SEQ + k0 + c8);
        }
        if (tid < 16) cp16(mA + s*256 + tid*16, mrow + k0 + tid*4);
        CP_COMMIT();
    };

    // load Q tile (fp16, 128 rows x 64 halves)
    #pragma unroll
    for (int i = 0; i < 8; i++) {
        int li = tid + i*128;
        int r = li >> 3, c8 = (li & 7) * 8;
        uint4 v = *(const uint4*)&qbaseH[(size_t)(q0 + r)*2048 + c8];
        *(uint4*)&Qs[r*PW + c8/2] = v;
    }

    issue(0, 0);
    issue(1, 64);

    float o[2][8][4];
    float m0r[2], m1r[2], l0[2], l1[2];
    #pragma unroll
    for (int sl = 0; sl < 2; sl++) {
        m0r[sl] = -1e30f; m1r[sl] = -1e30f; l0[sl] = 0.f; l1[sl] = 0.f;
        #pragma unroll
        for (int nf = 0; nf < 8; nf++)
            #pragma unroll
            for (int j = 0; j < 4; j++) o[sl][nf][j] = 0.f;
    }

    const int NT = SEQ / 64;
    for (int kt = 0; kt < NT; kt++) {
        // early issue: slot (kt+2)%3 was last read in iter kt-1 (sync'd)
        if (kt + 2 < NT) {
            issue((kt + 2) % 3, (kt + 2) * 64);
            CP_WAIT(2);
        } else if (kt + 1 < NT) {
            CP_WAIT(1);
        } else {
            CP_WAIT(0);
        }
        __syncthreads();

        int st = kt % 3;
        unsigned* Kb = Ks + st*KSTG;
        unsigned* Vb = Vs + st*VSTG;
        int*      Mb = Ms + st*64;

        // S = Q K^T  (fp16 k16)
        float s[2][8][4];
        #pragma unroll
        for (int sl = 0; sl < 2; sl++)
            #pragma unroll
            for (int nf = 0; nf < 8; nf++)
                #pragma unroll
                for (int j = 0; j < 4; j++) s[sl][nf][j] = 0.f;
        #pragma unroll
        for (int kk = 0; kk < 64; kk += 16) {
            int kw = kk >> 1;
            unsigned a[2][4];
            #pragma unroll
            for (int sl = 0; sl < 2; sl++) {
                int rA = rbase + 16*sl + gid;
                a[sl][0] = Qs[rA*PW + kw + tig];
                a[sl][1] = Qs[(rA+8)*PW + kw + tig];
                a[sl][2] = Qs[rA*PW + kw + 4 + tig];
                a[sl][3] = Qs[(rA+8)*PW + kw + 4 + tig];
            }
            #pragma unroll
            for (int nf = 0; nf < 8; nf++) {
                unsigned b0 = Kb[(nf*8 + gid)*PW + kw + tig];
                unsigned b1 = Kb[(nf*8 + gid)*PW + kw + 4 + tig];
                mma_f16(s[0][nf], a[0][0], a[0][1], a[0][2], a[0][3], b0, b1);
                mma_f16(s[1][nf], a[1][0], a[1][1], a[1][2], a[1][3], b0, b1);
            }
        }

        // mask + scale + online softmax + fp16 pack, per slab
        unsigned ph[2][8][2];
        #pragma unroll
        for (int sl = 0; sl < 2; sl++) {
            #pragma unroll
            for (int nf = 0; nf < 8; nf++) {
                int col = nf*8 + 2*tig;
                int mv0 = Mb[col], mv1 = Mb[col+1];
                s[sl][nf][0] = mv0 ? s[sl][nf][0]*0.125f : -1e30f;
                s[sl][nf][1] = mv1 ? s[sl][nf][1]*0.125f : -1e30f;
                s[sl][nf][2] = mv0 ? s[sl][nf][2]*0.125f : -1e30f;
                s[sl][nf][3] = mv1 ? s[sl][nf][3]*0.125f : -1e30f;
            }
            float rm0 = -1e30f, rm1 = -1e30f;
            #pragma unroll
            for (int nf = 0; nf < 8; nf++) {
                rm0 = fmaxf(rm0, fmaxf(s[sl][nf][0], s[sl][nf][1]));
                rm1 = fmaxf(rm1, fmaxf(s[sl][nf][2], s[sl][nf][3]));
            }
            rm0 = fmaxf(rm0, __shfl_xor_sync(0xffffffffu, rm0, 1));
            rm0 = fmaxf(rm0, __shfl_xor_sync(0xffffffffu, rm0, 2));
            rm1 = fmaxf(rm1, __shfl_xor_sync(0xffffffffu, rm1, 1));
            rm1 = fmaxf(rm1, __shfl_xor_sync(0xffffffffu, rm1, 2));

            float mn0 = fmaxf(m0r[sl], rm0), mn1 = fmaxf(m1r[sl], rm1);
            float sc0 = __expf(m0r[sl] - mn0), sc1 = __expf(m1r[sl] - mn1);
            m0r[sl] = mn0; m1r[sl] = mn1;

            float rs0 = 0.f, rs1 = 0.f;
            #pragma unroll
            for (int nf = 0; nf < 8; nf++) {
                s[sl][nf][0] = __expf(s[sl][nf][0] - mn0);
                s[sl][nf][1] = __expf(s[sl][nf][1] - mn0);
                s[sl][nf][2] = __expf(s[sl][nf][2] - mn1);
                s[sl][nf][3] = __expf(s[sl][nf][3] - mn1);
                rs0 += s[sl][nf][0] + s[sl][nf][1];
                rs1 += s[sl][nf][2] + s[sl][nf][3];
            }
            rs0 += __shfl_xor_sync(0xffffffffu, rs0, 1);
            rs0 += __shfl_xor_sync(0xffffffffu, rs0, 2);
            rs1 += __shfl_xor_sync(0xffffffffu, rs1, 1);
            rs1 += __shfl_xor_sync(0xffffffffu, rs1, 2);
            l0[sl] = l0[sl]*sc0 + rs0;
            l1[sl] = l1[sl]*sc1 + rs1;

            #pragma unroll
            for (int nf = 0; nf < 8; nf++) {
                o[sl][nf][0] *= sc0; o[sl][nf][1] *= sc0;
                o[sl][nf][2] *= sc1; o[sl][nf][3] *= sc1;
                ph[sl][nf][0] = packh2(s[sl][nf][0], s[sl][nf][1]);
                ph[sl][nf][1] = packh2(s[sl][nf][2], s[sl][nf][3]);
            }
        }

        // O += P @ V : register A-frags (no shfl), V frags shared per slab
        #pragma unroll
        for (int kk = 0; kk < 64; kk += 16) {
            int g0 = kk >> 3, g1 = g0 + 1;
            int kw = kk >> 1;
            #pragma unroll
            for (int nf = 0; nf < 8; nf++) {
                unsigned b0 = Vb[(nf*8 + gid)*PW + kw + tig];
                unsigned b1 = Vb[(nf*8 + gid)*PW + kw + 4 + tig];
                mma_f16(o[0][nf], ph[0][g0][0], ph[0][g0][1], ph[0][g1][0], ph[0][g1][1], b0, b1);
                mma_f16(o[1][nf], ph[1][g0][0], ph[1][g0][1], ph[1][g1][0], ph[1][g1][1], b0, b1);
            }
        }
        __syncthreads();
    }

    // epilogue: normalize, write fp16 (consumed by fp16 out-proj GEMM)
    #pragma unroll
    for (int sl = 0; sl < 2; sl++) {
        float inv0 = 1.f / l0[sl], inv1 = 1.f / l1[sl];
        int rA = rbase + sl*16 + gid, rB = rA + 8;
        #pragma unroll
        for (int nf = 0; nf < 8; nf++) {
            int col = nf*8 + 2*tig;
            size_t orow0 = (size_t)(b*SEQ + q0 + rA) * EMB + h*HDIM + col;
            size_t orow1 = (size_t)(b*SEQ + q0 + rB) * EMB + h*HDIM + col;
            __half2 h0 = __floats2half2_rn(o[sl][nf][0]*inv0, o[sl][nf][1]*inv0);
            __half2 h1 = __floats2half2_rn(o[sl][nf][2]*inv1, o[sl][nf][3]*inv1);
            *(__half2*)&g_attnh[orow0] = h0;
            *(__half2*)&g_attnh[orow1] = h1;
        }
    }
}

// ---------------- launch ---------------------------------------------------
extern "C" void kernel_launch(void* const* d_in, const int* in_sizes, int n_in,
                              void* d_out, int out_size) {
    const float* x      = (const float*)d_in[0];
    const int*   mask   = (const int*)  d_in[1];
    const float* Wqkv   = (const float*)d_in[2];
    const float* bqkv   = (const float*)d_in[3];
    const float* Wout   = (const float*)d_in[4];
    const float* bout   = (const float*)d_in[5];
    const float* diag   = (const float*)d_in[6];
    const float* alpha  = (const float*)d_in[7];
    const float* bias_h = (const float*)d_in[8];
    float* out = (float*)d_out;

    float*  vbuf;  cudaGetSymbolAddress((void**)&vbuf,  g_v);
    float*  Wf;    cudaGetSymbolAddress((void**)&Wf,    g_Wf);
    float*  bf;    cudaGetSymbolAddress((void**)&bf,    g_bf);
    __half* xh;    cudaGetSymbolAddress((void**)&xh,    g_xh);
    __half* WfT;   cudaGetSymbolAddress((void**)&WfT,   g_WfT);
    __half* WoT;   cudaGetSymbolAddress((void**)&WoT,   g_WoT);
    __half* qkh;   cudaGetSymbolAddress((void**)&qkh,   g_qkh);
    __half* attnh; cudaGetSymbolAddress((void**)&attnh, g_attnh);

    build_T_kernel<<<64, 64>>>(diag, alpha);
    {
        dim3 grid((QKV_N + 255)/256, EMB);
        fold_w_kernel<<<grid, 256>>>(Wqkv);
        fold_b_kernel<<<(QKV_N + 255)/256, 256>>>(bqkv, bias_h);
        int n4x = M_ROWS*EMB/4;
        h16_kernel<<<(n4x + 255)/256, 256>>>(x, xh, n4x);
        dim3 blk(32, 8);
        dim3 g1(QKV_N/32, EMB/32);
        transpose_h_kernel<<<g1, blk>>>(Wf, WfT, EMB, QKV_N);
        dim3 g2(EMB/32, EMB/32);
        transpose_h_kernel<<<g2, blk>>>(Wout, WoT, EMB, EMB);
    }

    cudaFuncSetAttribute(gemm_f16_kernel,
                         cudaFuncAttributeMaxDynamicSharedMemorySize, GEMM_SMEM);
    {   // QKV GEMM fp16: q/k -> g_qkh, v -> g_v
        dim3 grid(QKV_N/256, M_ROWS/128);
        gemm_f16_kernel<<<grid, 256, GEMM_SMEM>>>(xh, WfT, bf, vbuf, qkh,
                                                  M_ROWS, QKV_N, EMB, 1);
    }
    {   // V transpose -> g_vT
        dim3 blk(32, 8);
        dim3 grid(SEQ/32, 2, 32);
        vT_kernel<<<grid, blk>>>();
    }
    {   // attention (fp16, Bq=128, 3-stage)
        cudaFuncSetAttribute(attn_f16_kernel,
                             cudaFuncAttributeMaxDynamicSharedMemorySize, ATTN_SMEM);
        dim3 grid(BATCH*NHEAD, SEQ/128);
        attn_f16_kernel<<<grid, 128, ATTN_SMEM>>>(mask);
    }
    {   // output projection fp16 -> fp32 out
        dim3 grid(EMB/256, M_ROWS/128);
        gemm_f16_kernel<<<grid, 256, GEMM_SMEM>>>(attnh, WoT, bout, out, nullptr,
                                                  M_ROWS, EMB, EMB, 0);
    }
}